// round 2
// baseline (speedup 1.0000x reference)
#include <cuda_runtime.h>
#include <math.h>

// ---------------------------------------------------------------------------
// VectorQuantizer on GB300 (sm_103a)
//   x:        [32, 256, 32, 32] f32  (NCHW)   -> flat rows n=(b,h,w), dim c=256
//   codebook: [1024, 256] f32
// Outputs (concatenated f32): [loss(1), q_out(8388608 NCHW), perplexity(1), idx(32768)]
// ---------------------------------------------------------------------------

#define NROWS   32768      // 32 * 32 * 32
#define NCODES  1024
#define CDIM    256
#define QELEMS  8388608    // 32*256*32*32
#define GATHER_BLOCKS 4096

// Scratch (no cudaMalloc allowed): __device__ globals
__device__ float g_srow[NROWS];            // ||x_n||^2
__device__ float g_cc[NCODES];             // ||c_k||^2
__device__ float g_cbT[CDIM * NCODES];     // codebook transposed [k-dim][code]
__device__ int   g_best[NROWS];            // argmin index per row
__device__ int   g_counts[NCODES];         // histogram
__device__ float g_partials[GATHER_BLOCKS];// per-block squared-error sums

// ---------------------------------------------------------------------------
__global__ void zero_kernel() {
    int t = blockIdx.x * blockDim.x + threadIdx.x;
    if (t < NCODES) g_counts[t] = 0;
    if (t < GATHER_BLOCKS) g_partials[t] = 0.0f;
}

// ||x_n||^2, coalesced across warp (consecutive n = consecutive hw)
__global__ void prep_s_kernel(const float* __restrict__ x) {
    int n = blockIdx.x * blockDim.x + threadIdx.x;   // grid covers 32768
    int b  = n >> 10;
    int hw = n & 1023;
    const float* p = x + (size_t)b * 262144 + hw;
    float s = 0.0f;
    #pragma unroll 8
    for (int c = 0; c < CDIM; c++) {
        float v = p[(size_t)c << 10];
        s = __fmaf_rn(v, v, s);
    }
    g_srow[n] = s;
}

// transpose codebook into g_cbT[k][code] and compute ||c||^2
__global__ void prep_cb_kernel(const float* __restrict__ cb) {
    __shared__ float sh[256];
    int k = blockIdx.x;          // code
    int t = threadIdx.x;         // dim
    float v = cb[k * CDIM + t];
    g_cbT[(size_t)t * NCODES + k] = v;
    sh[t] = v * v;
    __syncthreads();
    for (int s = 128; s > 0; s >>= 1) {
        if (t < s) sh[t] += sh[t + s];
        __syncthreads();
    }
    if (t == 0) g_cc[k] = sh[0];
}

// ---------------------------------------------------------------------------
// Main: per block, 128 rows x all 1024 codes. Register-tiled f32 "GEMM" with
// fused argmin epilogue per 128-code tile.
//   block = 256 threads, tx = tid&15 (codes), ty = tid>>4 (rows)
//   per thread: 8 rows x 8 codes accumulators
// ---------------------------------------------------------------------------
__global__ void __launch_bounds__(256, 2)
vq_main_kernel(const float* __restrict__ x) {
    __shared__ float As[16][132];   // [k][row], padded
    __shared__ float Bs[16][132];   // [k][code], padded

    const int tid = threadIdx.x;
    const int tx  = tid & 15;
    const int ty  = tid >> 4;
    const int n0  = blockIdx.x * 128;
    const int b   = n0 >> 10;
    const int hw0 = n0 & 1023;                 // 128-aligned
    const float* xb = x + (size_t)b * 262144 + hw0;

    float sreg[8];
    #pragma unroll
    for (int i = 0; i < 8; i++) sreg[i] = g_srow[n0 + ty * 8 + i];

    float bestd[8];
    int   bestc[8];
    #pragma unroll
    for (int i = 0; i < 8; i++) { bestd[i] = 3.4e38f; bestc[i] = 0; }

    for (int ct = 0; ct < 8; ct++) {           // 8 code tiles of 128
        const int c0 = ct * 128;
        float acc[8][8];
        #pragma unroll
        for (int i = 0; i < 8; i++)
            #pragma unroll
            for (int j = 0; j < 8; j++) acc[i][j] = 0.0f;

        for (int k0 = 0; k0 < CDIM; k0 += 16) {
            __syncthreads();
            // load A tile (rows x 16 k) and B tile (codes x 16 k), 2 float4 each
            #pragma unroll
            for (int t = 0; t < 2; t++) {
                int j  = tid + t * 256;        // [0,512)
                int kk = j >> 5;
                int r4 = (j & 31) * 4;
                float4 va = *(const float4*)(xb + r4 + (size_t)(k0 + kk) * 1024);
                *(float4*)&As[kk][r4] = va;
                float4 vb = *(const float4*)(g_cbT + (size_t)(k0 + kk) * NCODES + c0 + r4);
                *(float4*)&Bs[kk][r4] = vb;
            }
            __syncthreads();

            #pragma unroll
            for (int kk = 0; kk < 16; kk++) {
                float4 a0 = *(float4*)&As[kk][ty * 8];
                float4 a1 = *(float4*)&As[kk][ty * 8 + 4];
                float4 b0 = *(float4*)&Bs[kk][tx * 8];
                float4 b1 = *(float4*)&Bs[kk][tx * 8 + 4];
                float av[8] = {a0.x, a0.y, a0.z, a0.w, a1.x, a1.y, a1.z, a1.w};
                float bv[8] = {b0.x, b0.y, b0.z, b0.w, b1.x, b1.y, b1.z, b1.w};
                #pragma unroll
                for (int i = 0; i < 8; i++)
                    #pragma unroll
                    for (int jj = 0; jj < 8; jj++)
                        acc[i][jj] = __fmaf_rn(av[i], bv[jj], acc[i][jj]);
            }
        }

        // epilogue: d = (s + cc) - 2*dot  (two explicit rounded adds, NO fma
        // contraction — must match the reference's rounding to ulp(~256))
        #pragma unroll
        for (int j = 0; j < 8; j++) {
            int c = c0 + tx * 8 + j;           // ascending codes per thread
            float ccv = g_cc[c];
            #pragma unroll
            for (int i = 0; i < 8; i++) {
                float t2 = __fadd_rn(sreg[i], ccv);
                float m  = __fmul_rn(2.0f, acc[i][j]);
                float d  = __fadd_rn(t2, -m);
                if (d < bestd[i]) { bestd[i] = d; bestc[i] = c; }  // strict < = first-index ties
            }
        }
    }

    // reduce across the 16 tx lanes sharing each row (lanes are contiguous in
    // half-warps since tid = ty*16 + tx). Tie -> smaller index.
    #pragma unroll
    for (int i = 0; i < 8; i++) {
        float v = bestd[i];
        int   c = bestc[i];
        #pragma unroll
        for (int off = 8; off > 0; off >>= 1) {
            float vo = __shfl_down_sync(0xffffffffu, v, off);
            int   co = __shfl_down_sync(0xffffffffu, c, off);
            if (vo < v || (vo == v && co < c)) { v = vo; c = co; }
        }
        if (tx == 0) g_best[n0 + ty * 8 + i] = c;
    }
}

// ---------------------------------------------------------------------------
__global__ void hist_kernel() {
    int n = blockIdx.x * blockDim.x + threadIdx.x;   // 32768
    atomicAdd(&g_counts[g_best[n]], 1);
}

// gather quantized values, write q_out (straight-through value = x + (q - x)),
// accumulate squared error deterministically into g_partials
__global__ void gather_kernel(const float* __restrict__ x,
                              const float* __restrict__ cb,
                              float* __restrict__ out, long long q_off) {
    __shared__ float sh[256];
    long long stride = (long long)gridDim.x * blockDim.x;
    float part = 0.0f;
    for (long long o = (long long)blockIdx.x * blockDim.x + threadIdx.x;
         o < QELEMS; o += stride) {
        int b  = (int)(o >> 18);
        int c  = (int)((o >> 10) & 255);
        int hw = (int)(o & 1023);
        int n  = (b << 10) + hw;
        int idx = g_best[n];
        float q  = cb[idx * CDIM + c];
        float xo = x[o];
        float diff = __fadd_rn(q, -xo);          // q - x
        part = __fmaf_rn(diff, diff, part);
        if (q_off >= 0) out[q_off + o] = __fadd_rn(xo, diff);  // x + (q - x)
    }
    sh[threadIdx.x] = part;
    __syncthreads();
    for (int s = 128; s > 0; s >>= 1) {
        if (threadIdx.x < s) sh[threadIdx.x] += sh[threadIdx.x + s];
        __syncthreads();
    }
    if (threadIdx.x == 0) g_partials[blockIdx.x] = sh[0];
}

__global__ void idxout_kernel(float* __restrict__ out, long long idx_off) {
    int n = blockIdx.x * blockDim.x + threadIdx.x;
    out[idx_off + n] = (float)g_best[n];
}

__global__ void finalize_kernel(float* __restrict__ out,
                                long long loss_off, long long perp_off) {
    __shared__ float sh[1024];
    int t = threadIdx.x;
    float s = 0.0f;
    #pragma unroll
    for (int j = 0; j < GATHER_BLOCKS / 1024; j++)
        s += g_partials[t * (GATHER_BLOCKS / 1024) + j];
    sh[t] = s;
    __syncthreads();
    for (int st = 512; st > 0; st >>= 1) {
        if (t < st) sh[t] += sh[t + st];
        __syncthreads();
    }
    float total = sh[0];
    __syncthreads();

    // perplexity
    float p = (float)g_counts[t] / (float)NROWS;
    sh[t] = p * logf(p + 1e-10f);
    __syncthreads();
    for (int st = 512; st > 0; st >>= 1) {
        if (t < st) sh[t] += sh[t + st];
        __syncthreads();
    }
    if (t == 0) {
        if (loss_off >= 0) out[loss_off] = 1.25f * (total / (float)QELEMS);
        if (perp_off >= 0) out[perp_off] = expf(-sh[0]);
    }
}

// ---------------------------------------------------------------------------
extern "C" void kernel_launch(void* const* d_in, const int* in_sizes, int n_in,
                              void* d_out, int out_size) {
    const float* x  = (const float*)d_in[0];   // [32,256,32,32]
    const float* cb = (const float*)d_in[1];   // [1024,256]
    float* out = (float*)d_out;

    long long loss_off = -1, q_off = -1, perp_off = -1, idx_off = -1;
    if (out_size == 1 + QELEMS + 1 + NROWS) {
        loss_off = 0; q_off = 1; perp_off = 1 + QELEMS; idx_off = 2 + QELEMS;
    } else if (out_size == QELEMS) {
        q_off = 0;
    } else if (out_size == QELEMS + NROWS) {
        q_off = 0; idx_off = QELEMS;
    } else if (out_size == NROWS) {
        idx_off = 0;
    } else {
        // default: full concatenated layout
        loss_off = 0; q_off = 1; perp_off = 1 + QELEMS; idx_off = 2 + QELEMS;
    }

    zero_kernel<<<GATHER_BLOCKS / 256, 256>>>();
    prep_s_kernel<<<NROWS / 256, 256>>>(x);
    prep_cb_kernel<<<NCODES, 256>>>(cb);
    vq_main_kernel<<<NROWS / 128, 256>>>(x);
    hist_kernel<<<NROWS / 256, 256>>>();
    gather_kernel<<<GATHER_BLOCKS, 256>>>(x, cb, out, q_off);
    if (idx_off >= 0) idxout_kernel<<<NROWS / 256, 256>>>(out, idx_off);
    if (loss_off >= 0 || perp_off >= 0)
        finalize_kernel<<<1, 1024>>>(out, loss_off, perp_off);
}